// round 2
// baseline (speedup 1.0000x reference)
#include <cuda_runtime.h>
#include <math.h>

// Problem constants
#define NN 4096
#define KK 64
#define AA 8
#define DD 128
#define NU_ 100000
#define NR_ 32
#define NA_ 5000

typedef unsigned long long ull;

// Packed fp32x2 FMA (Blackwell dual-FP32 pipe): d = a*b + c per 32-bit lane
#define FMA2(acc, a, b) \
    asm("fma.rn.f32x2 %0, %1, %2, %3;" : "=l"(acc) : "l"(a), "l"(b), "l"(acc))
// Broadcast one fp32 into both halves of a 64-bit packed operand
#define PACK2(dst, f) \
    asm("mov.b64 %0, {%1, %1};" : "=l"(dst) : "r"(__float_as_uint(f)))
#define UNPACK2(lo, hi, v) \
    asm("mov.b64 {%0, %1}, %2;" : "=f"(lo), "=f"(hi) : "l"(v))

// Scratch (device globals: allocation-free per harness rules)
__device__ float g_Tu[(size_t)NU_ * 256];   // u2e @ W1[256:384]   (102.4 MB)
__device__ float g_Ta[(size_t)NA_ * 256];   // ua2e @ W1[384:512]  (5.12 MB)
__device__ float g_Tr1[NR_ * 256];          // r2e @ W1[0:128]
__device__ float g_Tr2[NR_ * 256];          // r2e @ W1[128:256]
__device__ float g_se[NN * DD];             // u2e[nodes] @ A1[128:256] + ab1

// -------------------------------------------------------------------------
// Precompute: out[r][j] = sum_i emb[r][i] * Wb[i*256 + j],  j in [0,256)
// One block = 16 rows. 256 threads: tid&63 -> column quad (4 cols via 2 FFMA2),
// tid>>6 -> row group of 4. f32x2 packed math.
// -------------------------------------------------------------------------
__global__ __launch_bounds__(256) void table_kernel(
    const float* __restrict__ emb, const float* __restrict__ Wb,
    int rows, int which)
{
    float* out = (which == 0) ? g_Tu : (which == 1) ? g_Ta
               : (which == 2) ? g_Tr1 : g_Tr2;

    __shared__ float s_e[16][128];
    const int r0 = blockIdx.x * 16;
    const int tid = threadIdx.x;

    for (int i = tid; i < 16 * 128; i += 256) {
        int r = i >> 7, c = i & 127;
        int rr = r0 + r;
        s_e[r][c] = (rr < rows) ? emb[(size_t)rr * 128 + c] : 0.f;
    }
    __syncthreads();

    const int cq = tid & 63;          // column quad: d0 = cq*4
    const int rg = tid >> 6;          // row group: rows rg*4 .. rg*4+3
    const int d0 = cq * 4;

    ull acc[4][2];
    #pragma unroll
    for (int r = 0; r < 4; r++) { acc[r][0] = 0ULL; acc[r][1] = 0ULL; }

    #pragma unroll 2
    for (int i = 0; i < 128; i++) {
        const ull w01 = *(const ull*)(Wb + i * 256 + d0);
        const ull w23 = *(const ull*)(Wb + i * 256 + d0 + 2);
        #pragma unroll
        for (int r = 0; r < 4; r++) {
            ull hh; PACK2(hh, s_e[rg * 4 + r][i]);
            FMA2(acc[r][0], hh, w01);
            FMA2(acc[r][1], hh, w23);
        }
    }
    #pragma unroll
    for (int r = 0; r < 4; r++) {
        int rr = r0 + rg * 4 + r;
        if (rr < rows) {
            float4 o;
            UNPACK2(o.x, o.y, acc[r][0]);
            UNPACK2(o.z, o.w, acc[r][1]);
            *(float4*)(out + (size_t)rr * 256 + d0) = o;
        }
    }
}

// -------------------------------------------------------------------------
// Precompute per-node self-embedding attention term:
//   g_se[n][d] = ab1[d] + sum_i u2e[nodes[n]][i] * A1[(128+i)*128 + d]
// -------------------------------------------------------------------------
__global__ __launch_bounds__(128) void se_kernel(
    const int* __restrict__ nodes, const float* __restrict__ u2e,
    const float* __restrict__ A1, const float* __restrict__ ab1)
{
    const int n = blockIdx.x;
    const int d = threadIdx.x;
    __shared__ float s[128];
    s[d] = u2e[(size_t)nodes[n] * 128 + d];
    __syncthreads();
    float acc = ab1[d];
    #pragma unroll 4
    for (int i = 0; i < 128; i++)
        acc = fmaf(s[i], A1[(128 + i) * 128 + d], acc);
    g_se[n * 128 + d] = acc;
}

// -------------------------------------------------------------------------
// Main fused kernel: one block per node (grid 4096), 256 threads.
// GEMM phases use f32x2 packed FMA: thread = 4 output cols x 8 paths.
// smem: s_h1[64*256] | s_h[64*128] | misc. 102400 bytes total.
// -------------------------------------------------------------------------
__global__ __launch_bounds__(256, 2) void agg_kernel(
    const int* __restrict__ prel, const int* __restrict__ pnbr,
    const int* __restrict__ attrs,
    const float* __restrict__ b1, const float* __restrict__ W2,
    const float* __restrict__ b2, const float* __restrict__ A1,
    const float* __restrict__ A2, const float* __restrict__ A3,
    const float* __restrict__ ab2, const float* __restrict__ ab3,
    float* __restrict__ out)
{
    extern __shared__ float sm[];
    float* s_h1 = sm;                 // 16384 floats (h1, later a1 / a2)
    float* s_h  = sm + 16384;         // 8192 floats
    float* s_se = sm + 24576;         // 128
    float* s_A3 = sm + 24704;         // 128
    float* s_lg = sm + 24832;         // 64
    int*   s_rel  = (int*)(sm + 24896);   // 128 ints
    int*   s_nbr  = s_rel + 128;          // 64
    int*   s_attr = s_nbr + 64;           // 512   -> ends at float-index 25600

    float* s_a  = s_h1;               // a1 overlays h1[0:8192]
    float* s_a2 = s_h1 + 8192;        // a2 overlays h1[8192:16384]

    const int n = blockIdx.x;
    const int t = threadIdx.x;

    if (t < 128) s_rel[t] = prel[n * 128 + t];
    if (t < 64)  s_nbr[t] = pnbr[n * 64 + t];
    for (int i = t; i < 512; i += 256) s_attr[i] = attrs[n * 512 + i];
    if (t < 128) { s_se[t] = g_se[n * 128 + t]; s_A3[t] = A3[t]; }
    __syncthreads();

    // ---- Step 1: h1[k][:] = relu(b1 + Tr1[r0] + Tr2[r1] + Tu[nbr] + sum_a Ta[attr]) ----
    {
        const int ksub = t >> 6;      // 4 paths processed concurrently
        const int jj = t & 63;        // float4 column group (256 cols / 4)
        const float4* b1v = (const float4*)b1;
        for (int kb = 0; kb < 16; kb++) {
            const int k = kb * 4 + ksub;
            const int r0 = s_rel[2 * k], r1 = s_rel[2 * k + 1], nb = s_nbr[k];
            float4 acc = b1v[jj];
            float4 v;
            v = ((const float4*)(g_Tr1 + r0 * 256))[jj];
            acc.x += v.x; acc.y += v.y; acc.z += v.z; acc.w += v.w;
            v = ((const float4*)(g_Tr2 + r1 * 256))[jj];
            acc.x += v.x; acc.y += v.y; acc.z += v.z; acc.w += v.w;
            v = ((const float4*)(g_Tu + (size_t)nb * 256))[jj];
            acc.x += v.x; acc.y += v.y; acc.z += v.z; acc.w += v.w;
            #pragma unroll
            for (int a = 0; a < 8; a++) {
                v = ((const float4*)(g_Ta + (size_t)s_attr[k * 8 + a] * 256))[jj];
                acc.x += v.x; acc.y += v.y; acc.z += v.z; acc.w += v.w;
            }
            acc.x = fmaxf(acc.x, 0.f); acc.y = fmaxf(acc.y, 0.f);
            acc.z = fmaxf(acc.z, 0.f); acc.w = fmaxf(acc.w, 0.f);
            ((float4*)(s_h1 + k * 256))[jj] = acc;
        }
    }
    __syncthreads();

    // Common thread mapping for GEMM phases:
    const int q  = t & 31;            // column quad: d0 = q*4 (128 cols)
    const int g  = t >> 5;            // path group: paths g*8 .. g*8+7
    const int d0 = q * 4;

    // ---- Step 2: h[k][d] = relu(b2[d] + sum_j h1[k][j] * W2[j][d]) ----
    {
        ull acc[8][2];
        const ull b01 = *(const ull*)(b2 + d0);
        const ull b23 = *(const ull*)(b2 + d0 + 2);
        #pragma unroll
        for (int r = 0; r < 8; r++) { acc[r][0] = b01; acc[r][1] = b23; }
        const float* hb = s_h1 + g * 8 * 256;
        #pragma unroll 2
        for (int j = 0; j < 256; j++) {
            const ull w01 = *(const ull*)(W2 + j * 128 + d0);
            const ull w23 = *(const ull*)(W2 + j * 128 + d0 + 2);
            #pragma unroll
            for (int r = 0; r < 8; r++) {
                ull hh; PACK2(hh, hb[r * 256 + j]);
                FMA2(acc[r][0], hh, w01);
                FMA2(acc[r][1], hh, w23);
            }
        }
        #pragma unroll
        for (int r = 0; r < 8; r++) {
            float4 o;
            UNPACK2(o.x, o.y, acc[r][0]);
            UNPACK2(o.z, o.w, acc[r][1]);
            o.x = fmaxf(o.x, 0.f); o.y = fmaxf(o.y, 0.f);
            o.z = fmaxf(o.z, 0.f); o.w = fmaxf(o.w, 0.f);
            *(float4*)(s_h + (g * 8 + r) * 128 + d0) = o;
        }
    }
    __syncthreads();

    // ---- Step 3: a1[k][d] = relu(se[d] + sum_j h[k][j] * A1[j][d]) ----
    {
        ull acc[8][2];
        const ull s01 = *(const ull*)(s_se + d0);
        const ull s23 = *(const ull*)(s_se + d0 + 2);
        #pragma unroll
        for (int r = 0; r < 8; r++) { acc[r][0] = s01; acc[r][1] = s23; }
        const float* hb = s_h + g * 8 * 128;
        #pragma unroll 2
        for (int j = 0; j < 128; j++) {
            const ull w01 = *(const ull*)(A1 + j * 128 + d0);
            const ull w23 = *(const ull*)(A1 + j * 128 + d0 + 2);
            #pragma unroll
            for (int r = 0; r < 8; r++) {
                ull hh; PACK2(hh, hb[r * 128 + j]);
                FMA2(acc[r][0], hh, w01);
                FMA2(acc[r][1], hh, w23);
            }
        }
        #pragma unroll
        for (int r = 0; r < 8; r++) {
            float4 o;
            UNPACK2(o.x, o.y, acc[r][0]);
            UNPACK2(o.z, o.w, acc[r][1]);
            o.x = fmaxf(o.x, 0.f); o.y = fmaxf(o.y, 0.f);
            o.z = fmaxf(o.z, 0.f); o.w = fmaxf(o.w, 0.f);
            *(float4*)(s_a + (g * 8 + r) * 128 + d0) = o;
        }
    }
    __syncthreads();

    // ---- Step 4: a2[k][d] = relu(ab2[d] + sum_j a1[k][j] * A2[j][d]) ----
    {
        ull acc[8][2];
        const ull b01 = *(const ull*)(ab2 + d0);
        const ull b23 = *(const ull*)(ab2 + d0 + 2);
        #pragma unroll
        for (int r = 0; r < 8; r++) { acc[r][0] = b01; acc[r][1] = b23; }
        const float* ab = s_a + g * 8 * 128;
        #pragma unroll 2
        for (int j = 0; j < 128; j++) {
            const ull w01 = *(const ull*)(A2 + j * 128 + d0);
            const ull w23 = *(const ull*)(A2 + j * 128 + d0 + 2);
            #pragma unroll
            for (int r = 0; r < 8; r++) {
                ull hh; PACK2(hh, ab[r * 128 + j]);
                FMA2(acc[r][0], hh, w01);
                FMA2(acc[r][1], hh, w23);
            }
        }
        #pragma unroll
        for (int r = 0; r < 8; r++) {
            float4 o;
            UNPACK2(o.x, o.y, acc[r][0]);
            UNPACK2(o.z, o.w, acc[r][1]);
            o.x = fmaxf(o.x, 0.f); o.y = fmaxf(o.y, 0.f);
            o.z = fmaxf(o.z, 0.f); o.w = fmaxf(o.w, 0.f);
            *(float4*)(s_a2 + (g * 8 + r) * 128 + d0) = o;
        }
    }
    __syncthreads();

    // ---- Step 5: logits[k] = ab3 + a2[k] . A3 (warp-parallel) ----
    {
        const int wid = t >> 5, lane = t & 31;
        for (int kk = 0; kk < 8; kk++) {
            const int k = wid * 8 + kk;
            float acc = 0.f;
            #pragma unroll
            for (int ii = 0; ii < 4; ii++) {
                const int idx = ii * 32 + lane;
                acc = fmaf(s_a2[k * 128 + idx], s_A3[idx], acc);
            }
            #pragma unroll
            for (int off = 16; off; off >>= 1)
                acc += __shfl_down_sync(0xffffffffu, acc, off);
            if (lane == 0) s_lg[k] = acc + ab3[0];
        }
    }
    __syncthreads();

    // ---- Step 6: softmax over 64 logits (warp 0) ----
    if (t < 32) {
        float l0 = s_lg[t], l1 = s_lg[t + 32];
        float m = fmaxf(l0, l1);
        #pragma unroll
        for (int off = 16; off; off >>= 1)
            m = fmaxf(m, __shfl_xor_sync(0xffffffffu, m, off));
        float e0 = expf(l0 - m), e1 = expf(l1 - m);
        float s = e0 + e1;
        #pragma unroll
        for (int off = 16; off; off >>= 1)
            s += __shfl_xor_sync(0xffffffffu, s, off);
        const float inv = 1.f / s;
        s_lg[t] = e0 * inv;
        s_lg[t + 32] = e1 * inv;
    }
    __syncthreads();

    // ---- Step 7: out[n][d] = sum_k w[k] * h[k][d] ----
    if (t < 128) {
        float acc = 0.f;
        #pragma unroll 4
        for (int k = 0; k < 64; k++)
            acc = fmaf(s_lg[k], s_h[k * 128 + t], acc);
        out[n * 128 + t] = acc;
    }
}

// -------------------------------------------------------------------------
extern "C" void kernel_launch(void* const* d_in, const int* in_sizes, int n_in,
                              void* d_out, int out_size)
{
    const int*   nodes = (const int*)d_in[0];
    const int*   prel  = (const int*)d_in[1];
    const int*   pnbr  = (const int*)d_in[2];
    const int*   attrs = (const int*)d_in[3];
    const float* u2e   = (const float*)d_in[4];
    const float* r2e   = (const float*)d_in[5];
    const float* ua2e  = (const float*)d_in[6];
    const float* W1    = (const float*)d_in[7];
    const float* b1    = (const float*)d_in[8];
    const float* W2    = (const float*)d_in[9];
    const float* b2    = (const float*)d_in[10];
    const float* A1    = (const float*)d_in[11];
    const float* ab1   = (const float*)d_in[12];
    const float* A2    = (const float*)d_in[13];
    const float* ab2   = (const float*)d_in[14];
    const float* A3    = (const float*)d_in[15];
    const float* ab3   = (const float*)d_in[16];
    float* out = (float*)d_out;

    // Precompute folded layer-1 tables (exact linear decomposition of x@W1)
    table_kernel<<<(NU_ + 15) / 16, 256>>>(u2e,  W1 + 256 * 256, NU_, 0);
    table_kernel<<<(NA_ + 15) / 16, 256>>>(ua2e, W1 + 384 * 256, NA_, 1);
    table_kernel<<<2, 256>>>(r2e, W1,             NR_, 2);
    table_kernel<<<2, 256>>>(r2e, W1 + 128 * 256, NR_, 3);
    se_kernel<<<NN, 128>>>(nodes, u2e, A1, ab1);

    cudaFuncSetAttribute(agg_kernel,
                         cudaFuncAttributeMaxDynamicSharedMemorySize, 102400);
    agg_kernel<<<NN, 256, 102400>>>(prel, pnbr, attrs, b1, W2, b2,
                                    A1, A2, A3, ab2, ab3, out);
}

// round 4
// speedup vs baseline: 1.6823x; 1.6823x over previous
#include <cuda_runtime.h>
#include <math.h>
#include <stdint.h>

// Problem constants
#define NN 4096
#define NU_ 100000
#define NR_ 32
#define NA_ 5000

// ---------------- device global scratch (allocation-free) ----------------
__device__ float g_Tu[(size_t)NU_ * 256];   // u2e @ W1[256:384]
__device__ float g_Ta[(size_t)NA_ * 256];   // ua2e @ W1[384:512]
__device__ float g_Tr1[NR_ * 256];          // r2e @ W1[0:128]
__device__ float g_Tr2[NR_ * 256];          // r2e @ W1[128:256]
__device__ float g_se[NN * 128];            // u2e[nodes] @ A1[128:256] + ab1
// Weight fragments for mma.sync m16n8k8 tf32, pre-split hi/lo.
// Layout: [ks][nt(16)][lane(32)] -> float4 {bh0, bh1, bl0, bl1}
__device__ float4 g_W2f[32 * 16 * 32];      // W2 [256x128]: 32 k-steps
__device__ float4 g_A1f[16 * 16 * 32];      // A1[0:128][128]: 16 k-steps
__device__ float4 g_A2f[16 * 16 * 32];      // A2 [128x128]: 16 k-steps

// ---------------- helpers ----------------
__device__ __forceinline__ float tf32_hif(float x) {
    return __int_as_float(__float_as_int(x) & 0xffffe000);
}
__device__ __forceinline__ uint32_t tf32_bits(float x) {
    return __float_as_uint(x) & 0xffffe000u;
}
__device__ __forceinline__ void mma8(float c[4],
    uint32_t a0, uint32_t a1, uint32_t a2, uint32_t a3,
    uint32_t b0, uint32_t b1)
{
    asm volatile(
        "mma.sync.aligned.m16n8k8.row.col.f32.tf32.tf32.f32 "
        "{%0,%1,%2,%3}, {%4,%5,%6,%7}, {%8,%9}, {%0,%1,%2,%3};"
        : "+f"(c[0]), "+f"(c[1]), "+f"(c[2]), "+f"(c[3])
        : "r"(a0), "r"(a1), "r"(a2), "r"(a3), "r"(b0), "r"(b1));
}

// ---------------- SMEM layout (float indices) ----------------
#define OFF_B1   0      // 256
#define OFF_B2   256    // 128
#define OFF_SE   384    // 128
#define OFF_AB2  512    // 128
#define OFF_A3   640    // 128
#define OFF_LGP  768    // 128  ([2][64] partial logits)
#define OFF_LG   896    // 64
#define OFF_REL  960    // 128 ints
#define OFF_NBR  1088   // 64 ints
#define OFF_ATT  1152   // 512 ints -> ends 1664
#define OFF_H1   1664   // 64 x 260 = 16640 -> ends 18304  (a1 overlays, stride 132)
#define OFF_H    18304  // 64 x 132 = 8448  -> ends 26752
#define H1S      260
#define HS       132
#define SMEM_FLOATS 26752
#define SMEM_BYTES  (SMEM_FLOATS * 4)

// ---------------- Precompute kernels (scalar, proven in R1) ----------------
__global__ __launch_bounds__(256) void table_kernel(
    const float* __restrict__ emb, const float* __restrict__ Wb, int rows, int which)
{
    float* out = (which == 0) ? g_Tu : (which == 1) ? g_Ta : (which == 2) ? g_Tr1 : g_Tr2;
    __shared__ float s_e[16][128];
    const int r0 = blockIdx.x * 16;
    const int tid = threadIdx.x;
    for (int i = tid; i < 16 * 128; i += 256) {
        int r = i >> 7, c = i & 127;
        int rr = r0 + r;
        s_e[r][c] = (rr < rows) ? emb[(size_t)rr * 128 + c] : 0.f;
    }
    __syncthreads();
    float acc[16];
    #pragma unroll
    for (int r = 0; r < 16; r++) acc[r] = 0.f;
    const int j = tid;
    #pragma unroll 2
    for (int i = 0; i < 128; i++) {
        float w = Wb[i * 256 + j];
        #pragma unroll
        for (int r = 0; r < 16; r++) acc[r] = fmaf(s_e[r][i], w, acc[r]);
    }
    #pragma unroll
    for (int r = 0; r < 16; r++) {
        int rr = r0 + r;
        if (rr < rows) out[(size_t)rr * 256 + j] = acc[r];
    }
}

__global__ __launch_bounds__(128) void se_kernel(
    const int* __restrict__ nodes, const float* __restrict__ u2e,
    const float* __restrict__ A1, const float* __restrict__ ab1)
{
    const int n = blockIdx.x;
    const int d = threadIdx.x;
    __shared__ float s[128];
    s[d] = u2e[(size_t)nodes[n] * 128 + d];
    __syncthreads();
    float acc = ab1[d];
    #pragma unroll 4
    for (int i = 0; i < 128; i++) acc = fmaf(s[i], A1[(128 + i) * 128 + d], acc);
    g_se[n * 128 + d] = acc;
}

// Build B fragments (hi/lo tf32 split) for the three weight matrices.
// Fragment mapping for mma.m16n8k8 row.col: b0 = B[k0 + (lane&3)][n0 + (lane>>2)],
// b1 = B[k0 + (lane&3) + 4][same n]. B given row-major [K][N], N = 128.
__global__ __launch_bounds__(256) void frag_kernel(
    const float* __restrict__ W2, const float* __restrict__ A1,
    const float* __restrict__ A2)
{
    int idx = blockIdx.x * 256 + threadIdx.x;   // 32768 total
    const float* W;
    float4* out;
    int j;
    if (idx < 16384)      { W = W2; out = g_W2f; j = idx; }
    else if (idx < 24576) { W = A1; out = g_A1f; j = idx - 16384; }
    else if (idx < 32768) { W = A2; out = g_A2f; j = idx - 24576; }
    else return;
    const int ks = j >> 9;            // 512 entries per k-step (16 nt x 32 lanes)
    const int rem = j & 511;
    const int nt = rem >> 5;
    const int lane = rem & 31;
    const int k = ks * 8 + (lane & 3);
    const int n = nt * 8 + (lane >> 2);
    const float x0 = W[k * 128 + n];
    const float x1 = W[(k + 4) * 128 + n];
    const float h0 = tf32_hif(x0), h1 = tf32_hif(x1);
    float4 o;
    o.x = h0;
    o.y = h1;
    o.z = tf32_hif(x0 - h0);
    o.w = tf32_hif(x1 - h1);
    out[j] = o;
}

// ---------------- warp-level 16x64 GEMM (3xTF32) ----------------
// As: warp's row-tile base (16 rows, stride astride). Bf: fragment array
// ([ks][16 nt][32 lane]). nt_base selects this warp's 8 n-tiles.
__device__ __forceinline__ void warp_gemm(
    const float* __restrict__ As, int astride, int ksteps,
    const float4* __restrict__ Bf, int nt_base,
    int gid, int tid4, int lane, float acc[8][4])
{
    #pragma unroll
    for (int i = 0; i < 8; i++)
        #pragma unroll
        for (int c = 0; c < 4; c++) acc[i][c] = 0.f;

    for (int ks = 0; ks < ksteps; ks++) {
        const float* a0p = As + gid * astride + ks * 8 + tid4;
        const float* a1p = As + (gid + 8) * astride + ks * 8 + tid4;
        const float x0 = a0p[0], x1 = a1p[0], x2 = a0p[4], x3 = a1p[4];
        const uint32_t ah0 = tf32_bits(x0), ah1 = tf32_bits(x1);
        const uint32_t ah2 = tf32_bits(x2), ah3 = tf32_bits(x3);
        const uint32_t al0 = tf32_bits(x0 - __uint_as_float(ah0));
        const uint32_t al1 = tf32_bits(x1 - __uint_as_float(ah1));
        const uint32_t al2 = tf32_bits(x2 - __uint_as_float(ah2));
        const uint32_t al3 = tf32_bits(x3 - __uint_as_float(ah3));
        const float4* bp = Bf + (ks * 16 + nt_base) * 32 + lane;
        #pragma unroll
        for (int nt = 0; nt < 8; nt++) {
            const float4 b = bp[nt * 32];
            const uint32_t bh0 = __float_as_uint(b.x), bh1 = __float_as_uint(b.y);
            const uint32_t bl0 = __float_as_uint(b.z), bl1 = __float_as_uint(b.w);
            mma8(acc[nt], ah0, ah1, ah2, ah3, bh0, bh1);
            mma8(acc[nt], ah0, ah1, ah2, ah3, bl0, bl1);
            mma8(acc[nt], al0, al1, al2, al3, bh0, bh1);
        }
    }
}

// Epilogue: bias + relu + store to smem (row-major, stride dstride).
// C mapping: c0=[gid][2t4], c1=[gid][2t4+1], c2=[gid+8][2t4], c3=[gid+8][2t4+1]
__device__ __forceinline__ void warp_epilogue(
    const float acc[8][4], const float* __restrict__ bias,
    float* __restrict__ dst, int dstride, int rt, int nt_base, int gid, int tid4)
{
    const int row0 = rt * 16 + gid;
    #pragma unroll
    for (int nt = 0; nt < 8; nt++) {
        const int col = (nt_base + nt) * 8 + 2 * tid4;
        const float b0 = bias[col], b1 = bias[col + 1];
        float2 v0, v1;
        v0.x = fmaxf(acc[nt][0] + b0, 0.f);
        v0.y = fmaxf(acc[nt][1] + b1, 0.f);
        v1.x = fmaxf(acc[nt][2] + b0, 0.f);
        v1.y = fmaxf(acc[nt][3] + b1, 0.f);
        *(float2*)(dst + row0 * dstride + col) = v0;
        *(float2*)(dst + (row0 + 8) * dstride + col) = v1;
    }
}

// ---------------- Fused kernel: one CTA = one node (64 paths) ----------------
__global__ __launch_bounds__(256, 2) void agg_mma_kernel(
    const int* __restrict__ prel, const int* __restrict__ pnbr,
    const int* __restrict__ attrs,
    const float* __restrict__ b1, const float* __restrict__ b2,
    const float* __restrict__ ab2, const float* __restrict__ A3,
    const float* __restrict__ ab3, float* __restrict__ out)
{
    extern __shared__ float sm[];
    const int n = blockIdx.x;
    const int t = threadIdx.x;
    const int w = t >> 5, lane = t & 31;
    const int gid = lane >> 2, tid4 = lane & 3;
    const int rt = w & 3;          // row tile (16 rows)
    const int ch = w >> 2;         // col half (8 n-tiles)
    const int nt_base = ch * 8;

    int* s_rel = (int*)(sm + OFF_REL);
    int* s_nbr = (int*)(sm + OFF_NBR);
    int* s_att = (int*)(sm + OFF_ATT);

    // preload per-node / per-layer constants
    sm[OFF_B1 + t] = b1[t];
    if (t < 128) {
        sm[OFF_B2 + t] = b2[t];
        sm[OFF_SE + t] = g_se[n * 128 + t];
        sm[OFF_AB2 + t] = ab2[t];
        sm[OFF_A3 + t] = A3[t];
        s_rel[t] = prel[n * 128 + t];
    }
    if (t < 64) s_nbr[t] = pnbr[n * 64 + t];
    for (int i = t; i < 512; i += 256) s_att[i] = attrs[n * 512 + i];
    __syncthreads();

    // ---- gather: h1[k][0:256] = relu(b1 + Tr1 + Tr2 + Tu + sum_a Ta) ----
    {
        float* s_h1 = sm + OFF_H1;
        const int ks = t >> 6;             // 4 paths concurrently
        const int jj = t & 63;             // float4 column group
        for (int kb = 0; kb < 16; kb++) {
            const int k = kb * 4 + ks;
            const int r0 = s_rel[2 * k], r1 = s_rel[2 * k + 1], nb = s_nbr[k];
            float4 acc = *(const float4*)(sm + OFF_B1 + jj * 4);
            float4 v;
            v = ((const float4*)(g_Tr1 + r0 * 256))[jj];
            acc.x += v.x; acc.y += v.y; acc.z += v.z; acc.w += v.w;
            v = ((const float4*)(g_Tr2 + r1 * 256))[jj];
            acc.x += v.x; acc.y += v.y; acc.z += v.z; acc.w += v.w;
            v = ((const float4*)(g_Tu + (size_t)nb * 256))[jj];
            acc.x += v.x; acc.y += v.y; acc.z += v.z; acc.w += v.w;
            #pragma unroll
            for (int a = 0; a < 8; a++) {
                v = ((const float4*)(g_Ta + (size_t)s_att[k * 8 + a] * 256))[jj];
                acc.x += v.x; acc.y += v.y; acc.z += v.z; acc.w += v.w;
            }
            acc.x = fmaxf(acc.x, 0.f); acc.y = fmaxf(acc.y, 0.f);
            acc.z = fmaxf(acc.z, 0.f); acc.w = fmaxf(acc.w, 0.f);
            ((float4*)(s_h1 + k * H1S))[jj] = acc;
        }
    }
    __syncthreads();

    float acc[8][4];

    // ---- GEMM1: h = relu(h1 @ W2 + b2)   [64x256]@[256x128] ----
    warp_gemm(sm + OFF_H1 + rt * 16 * H1S, H1S, 32, g_W2f, nt_base,
              gid, tid4, lane, acc);
    warp_epilogue(acc, sm + OFF_B2, sm + OFF_H, HS, rt, nt_base, gid, tid4);
    __syncthreads();

    // ---- GEMM2: a1 = relu(h @ A1[0:128] + se)  (a1 overlays h1 region) ----
    warp_gemm(sm + OFF_H + rt * 16 * HS, HS, 16, g_A1f, nt_base,
              gid, tid4, lane, acc);
    warp_epilogue(acc, sm + OFF_SE, sm + OFF_H1, HS, rt, nt_base, gid, tid4);
    __syncthreads();

    // ---- GEMM3: a2 = relu(a1 @ A2 + ab2); logits fused (a2 not stored) ----
    warp_gemm(sm + OFF_H1 + rt * 16 * HS, HS, 16, g_A2f, nt_base,
              gid, tid4, lane, acc);
    {
        float p0 = 0.f, p1 = 0.f;
        #pragma unroll
        for (int nt = 0; nt < 8; nt++) {
            const int col = (nt_base + nt) * 8 + 2 * tid4;
            const float b0 = sm[OFF_AB2 + col], b1v = sm[OFF_AB2 + col + 1];
            const float w0 = sm[OFF_A3 + col], w1 = sm[OFF_A3 + col + 1];
            p0 = fmaf(fmaxf(acc[nt][0] + b0, 0.f), w0, p0);
            p0 = fmaf(fmaxf(acc[nt][1] + b1v, 0.f), w1, p0);
            p1 = fmaf(fmaxf(acc[nt][2] + b0, 0.f), w0, p1);
            p1 = fmaf(fmaxf(acc[nt][3] + b1v, 0.f), w1, p1);
        }
        p0 += __shfl_xor_sync(0xffffffffu, p0, 1);
        p0 += __shfl_xor_sync(0xffffffffu, p0, 2);
        p1 += __shfl_xor_sync(0xffffffffu, p1, 1);
        p1 += __shfl_xor_sync(0xffffffffu, p1, 2);
        if (tid4 == 0) {
            sm[OFF_LGP + ch * 64 + rt * 16 + gid] = p0;
            sm[OFF_LGP + ch * 64 + rt * 16 + gid + 8] = p1;
        }
    }
    __syncthreads();

    // ---- softmax over 64 logits (warp 0) ----
    if (t < 32) {
        const float a3b = ab3[0];
        float l0 = a3b + sm[OFF_LGP + t] + sm[OFF_LGP + 64 + t];
        float l1 = a3b + sm[OFF_LGP + t + 32] + sm[OFF_LGP + 96 + t];
        float m = fmaxf(l0, l1);
        #pragma unroll
        for (int off = 16; off; off >>= 1)
            m = fmaxf(m, __shfl_xor_sync(0xffffffffu, m, off));
        float e0 = expf(l0 - m), e1 = expf(l1 - m);
        float s = e0 + e1;
        #pragma unroll
        for (int off = 16; off; off >>= 1)
            s += __shfl_xor_sync(0xffffffffu, s, off);
        const float inv = 1.f / s;
        sm[OFF_LG + t] = e0 * inv;
        sm[OFF_LG + t + 32] = e1 * inv;
    }
    __syncthreads();

    // ---- out[n][d] = sum_k w[k] * h[k][d] ----
    if (t < 128) {
        const float* hb = sm + OFF_H;
        float acc2 = 0.f;
        #pragma unroll 4
        for (int k = 0; k < 64; k++)
            acc2 = fmaf(sm[OFF_LG + k], hb[k * HS + t], acc2);
        out[(size_t)n * 128 + t] = acc2;
    }
}

// -------------------------------------------------------------------------
extern "C" void kernel_launch(void* const* d_in, const int* in_sizes, int n_in,
                              void* d_out, int out_size)
{
    const int*   nodes = (const int*)d_in[0];
    const int*   prel  = (const int*)d_in[1];
    const int*   pnbr  = (const int*)d_in[2];
    const int*   attrs = (const int*)d_in[3];
    const float* u2e   = (const float*)d_in[4];
    const float* r2e   = (const float*)d_in[5];
    const float* ua2e  = (const float*)d_in[6];
    const float* W1    = (const float*)d_in[7];
    const float* b1    = (const float*)d_in[8];
    const float* W2    = (const float*)d_in[9];
    const float* b2    = (const float*)d_in[10];
    const float* A1    = (const float*)d_in[11];
    const float* ab1   = (const float*)d_in[12];
    const float* A2    = (const float*)d_in[13];
    const float* ab2   = (const float*)d_in[14];
    const float* A3    = (const float*)d_in[15];
    const float* ab3   = (const float*)d_in[16];
    float* out = (float*)d_out;

    // Folded layer-1 tables (exact linear decomposition of x@W1)
    table_kernel<<<(NU_ + 15) / 16, 256>>>(u2e,  W1 + 256 * 256, NU_, 0);
    table_kernel<<<(NA_ + 15) / 16, 256>>>(ua2e, W1 + 384 * 256, NA_, 1);
    table_kernel<<<2, 256>>>(r2e, W1,             NR_, 2);
    table_kernel<<<2, 256>>>(r2e, W1 + 128 * 256, NR_, 3);
    se_kernel<<<NN, 128>>>(nodes, u2e, A1, ab1);
    frag_kernel<<<128, 256>>>(W2, A1, A2);

    cudaFuncSetAttribute(agg_mma_kernel,
                         cudaFuncAttributeMaxDynamicSharedMemorySize, SMEM_BYTES);
    agg_mma_kernel<<<NN, 256, SMEM_BYTES>>>(prel, pnbr, attrs,
                                            b1, b2, ab2, A3, ab3, out);
}

// round 5
// speedup vs baseline: 2.0593x; 1.2241x over previous
#include <cuda_runtime.h>
#include <math.h>
#include <stdint.h>

// Problem constants
#define NN 4096
#define NU_ 100000
#define NR_ 32
#define NA_ 5000

// ---------------- device global scratch (allocation-free) ----------------
__device__ float g_Tu[(size_t)NU_ * 256];   // u2e @ W1[256:384]
__device__ float g_Ta[(size_t)NA_ * 256];   // ua2e @ W1[384:512]
__device__ float g_Tr1[NR_ * 256];          // r2e @ W1[0:128]
__device__ float g_Tr2[NR_ * 256];          // r2e @ W1[128:256]
__device__ float g_se[NN * 128];            // u2e[nodes] @ A1[128:256] + ab1
// Weight fragments for mma.sync m16n8k8 tf32, pre-split hi/lo.
// float4 = {bh0, bh1, bl0, bl1}
__device__ float4 g_W2f[32 * 16 * 32];      // W2 [256x128]: [ks][nt16][lane]
__device__ float4 g_A1f[16 * 16 * 32];      // A1[0:128][128]
__device__ float4 g_A2f[16 * 16 * 32];      // A2 [128x128]
__device__ float4 g_W1f[4 * 16 * 32 * 32];  // W1 [512x256] as 4 parts: [p][ks][nt32][lane]

// ---------------- helpers ----------------
__device__ __forceinline__ float tf32_hif(float x) {
    return __int_as_float(__float_as_int(x) & 0xffffe000);
}
__device__ __forceinline__ uint32_t tf32_bits(float x) {
    return __float_as_uint(x) & 0xffffe000u;
}
__device__ __forceinline__ void mma8(float c[4],
    uint32_t a0, uint32_t a1, uint32_t a2, uint32_t a3,
    uint32_t b0, uint32_t b1)
{
    asm volatile(
        "mma.sync.aligned.m16n8k8.row.col.f32.tf32.tf32.f32 "
        "{%0,%1,%2,%3}, {%4,%5,%6,%7}, {%8,%9}, {%0,%1,%2,%3};"
        : "+f"(c[0]), "+f"(c[1]), "+f"(c[2]), "+f"(c[3])
        : "r"(a0), "r"(a1), "r"(a2), "r"(a3), "r"(b0), "r"(b1));
}

// Generic warp-level 16x(NT*8) GEMM with 3xTF32 splitting.
// As: warp row-tile base (16 rows, stride astride).
// Bf: fragment array [ks][ntot][32]; this warp uses nt_base..nt_base+NT-1.
template<int NT>
__device__ __forceinline__ void warp_gemm_g(
    const float* __restrict__ As, int astride, int ksteps,
    const float4* __restrict__ Bf, int ntot, int nt_base,
    int gid, int tid4, int lane, float acc[NT][4])
{
    #pragma unroll
    for (int i = 0; i < NT; i++)
        #pragma unroll
        for (int c = 0; c < 4; c++) acc[i][c] = 0.f;

    for (int ks = 0; ks < ksteps; ks++) {
        const float* a0p = As + gid * astride + ks * 8 + tid4;
        const float* a1p = As + (gid + 8) * astride + ks * 8 + tid4;
        const float x0 = a0p[0], x1 = a1p[0], x2 = a0p[4], x3 = a1p[4];
        const uint32_t ah0 = tf32_bits(x0), ah1 = tf32_bits(x1);
        const uint32_t ah2 = tf32_bits(x2), ah3 = tf32_bits(x3);
        const uint32_t al0 = tf32_bits(x0 - __uint_as_float(ah0));
        const uint32_t al1 = tf32_bits(x1 - __uint_as_float(ah1));
        const uint32_t al2 = tf32_bits(x2 - __uint_as_float(ah2));
        const uint32_t al3 = tf32_bits(x3 - __uint_as_float(ah3));
        const float4* bp = Bf + (ks * ntot + nt_base) * 32 + lane;
        #pragma unroll
        for (int nt = 0; nt < NT; nt++) {
            const float4 b = __ldg(bp + nt * 32);
            const uint32_t bh0 = __float_as_uint(b.x), bh1 = __float_as_uint(b.y);
            const uint32_t bl0 = __float_as_uint(b.z), bl1 = __float_as_uint(b.w);
            mma8(acc[nt], ah0, ah1, ah2, ah3, bh0, bh1);
            mma8(acc[nt], ah0, ah1, ah2, ah3, bl0, bl1);
            mma8(acc[nt], al0, al1, al2, al3, bh0, bh1);
        }
    }
}

// ---------------- SMEM layout for agg (float indices) ----------------
#define OFF_B1   0      // 256
#define OFF_B2   256    // 128
#define OFF_SE   384    // 128
#define OFF_AB2  512    // 128
#define OFF_A3   640    // 128
#define OFF_LGP  768    // 128
#define OFF_LG   896    // 64
#define OFF_REL  960    // 128 ints
#define OFF_NBR  1088   // 64 ints
#define OFF_ATT  1152   // 512 ints
#define OFF_H1   1664   // 64 x 260
#define OFF_H    18304  // 64 x 132
#define H1S      260
#define HS       132
#define SMEM_FLOATS 26752
#define SMEM_BYTES  (SMEM_FLOATS * 4)

// ---------------- Fragment builders ----------------
// b0 = B[k0+(lane&3)][n0+(lane>>2)], b1 = B[k0+(lane&3)+4][n], B row-major [K][N].
__global__ __launch_bounds__(256) void frag_kernel(
    const float* __restrict__ W2, const float* __restrict__ A1,
    const float* __restrict__ A2)
{
    int idx = blockIdx.x * 256 + threadIdx.x;   // 32768 total
    const float* W;
    float4* out;
    int j;
    if (idx < 16384)      { W = W2; out = g_W2f; j = idx; }
    else if (idx < 24576) { W = A1; out = g_A1f; j = idx - 16384; }
    else if (idx < 32768) { W = A2; out = g_A2f; j = idx - 24576; }
    else return;
    const int ks = j >> 9;
    const int rem = j & 511;
    const int nt = rem >> 5;
    const int lane = rem & 31;
    const int k = ks * 8 + (lane & 3);
    const int n = nt * 8 + (lane >> 2);
    const float x0 = W[k * 128 + n];
    const float x1 = W[(k + 4) * 128 + n];
    const float h0 = tf32_hif(x0), h1 = tf32_hif(x1);
    float4 o;
    o.x = h0; o.y = h1;
    o.z = tf32_hif(x0 - h0);
    o.w = tf32_hif(x1 - h1);
    out[j] = o;
}

// W1 [512][256] row-major -> 4 parts of [128][256], fragments with ntot=32.
__global__ __launch_bounds__(256) void frag_w1_kernel(const float* __restrict__ W1)
{
    int idx = blockIdx.x * 256 + threadIdx.x;   // 65536 total
    if (idx >= 65536) return;
    const int p = idx >> 14;            // part 0..3
    const int j = idx & 16383;
    const int ks = j >> 10;             // 32 nt x 32 lane = 1024 per ks
    const int rem = j & 1023;
    const int nt = rem >> 5;
    const int lane = rem & 31;
    const int k = ks * 8 + (lane & 3);
    const int n = nt * 8 + (lane >> 2);
    const float x0 = W1[(p * 128 + k) * 256 + n];
    const float x1 = W1[(p * 128 + k + 4) * 256 + n];
    const float h0 = tf32_hif(x0), h1 = tf32_hif(x1);
    float4 o;
    o.x = h0; o.y = h1;
    o.z = tf32_hif(x0 - h0);
    o.w = tf32_hif(x1 - h1);
    g_W1f[p * 16384 + j] = o;
}

// ---------------- se precompute (scalar, fast: 4096 blocks) ----------------
__global__ __launch_bounds__(128) void se_kernel(
    const int* __restrict__ nodes, const float* __restrict__ u2e,
    const float* __restrict__ A1, const float* __restrict__ ab1)
{
    const int n = blockIdx.x;
    const int d = threadIdx.x;
    __shared__ float s[128];
    s[d] = u2e[(size_t)nodes[n] * 128 + d];
    __syncthreads();
    float acc = ab1[d];
    #pragma unroll 4
    for (int i = 0; i < 128; i++) acc = fmaf(s[i], A1[(128 + i) * 128 + d], acc);
    g_se[n * 128 + d] = acc;
}

// ---------------- Unified tensor-core table kernel ----------------
// Computes all four folded tables T = emb @ W1part ([rows x 128] @ [128 x 256]).
// CTA = 64 rows. Segments: [0,1563) Tu | [1563,1642) Ta | 1642 Tr1 | 1643 Tr2.
#define TU_CTAS 1563
#define TA_CTAS 79
__global__ __launch_bounds__(256) void mma_table_kernel(
    const float* __restrict__ u2e, const float* __restrict__ ua2e,
    const float* __restrict__ r2e)
{
    __shared__ float s_a[64 * 132];
    const int b = blockIdx.x;
    const int t = threadIdx.x;

    const float* emb; float* out; const float4* Bf; int rows; int row0;
    if (b < TU_CTAS)            { emb = u2e;  out = g_Tu;  Bf = g_W1f + 2 * 16384; rows = NU_; row0 = b * 64; }
    else if (b < TU_CTAS + TA_CTAS) { emb = ua2e; out = g_Ta;  Bf = g_W1f + 3 * 16384; rows = NA_; row0 = (b - TU_CTAS) * 64; }
    else if (b == TU_CTAS + TA_CTAS) { emb = r2e;  out = g_Tr1; Bf = g_W1f;             rows = NR_; row0 = 0; }
    else                         { emb = r2e;  out = g_Tr2; Bf = g_W1f + 1 * 16384; rows = NR_; row0 = 0; }

    // load 64 rows x 128 cols (zero-pad invalid rows)
    for (int i = t; i < 64 * 32; i += 256) {
        const int r = i >> 5, c4 = i & 31;
        float4 v = make_float4(0.f, 0.f, 0.f, 0.f);
        if (row0 + r < rows)
            v = *(const float4*)(emb + (size_t)(row0 + r) * 128 + c4 * 4);
        *(float4*)(s_a + r * 132 + c4 * 4) = v;
    }
    __syncthreads();

    const int w = t >> 5, lane = t & 31;
    const int gid = lane >> 2, tid4 = lane & 3;
    const int rt = w & 3;              // 16-row tile
    const int ch = w >> 2;             // column half: 16 nt = 128 cols
    const int nt_base = ch * 16;

    float acc[16][4];
    warp_gemm_g<16>(s_a + rt * 16 * 132, 132, 16, Bf, 32, nt_base,
                    gid, tid4, lane, acc);

    const int r0 = rt * 16 + gid;
    #pragma unroll
    for (int nt = 0; nt < 16; nt++) {
        const int col = (nt_base + nt) * 8 + 2 * tid4;
        if (row0 + r0 < rows) {
            float2 v; v.x = acc[nt][0]; v.y = acc[nt][1];
            *(float2*)(out + (size_t)(row0 + r0) * 256 + col) = v;
        }
        if (row0 + r0 + 8 < rows) {
            float2 v; v.x = acc[nt][2]; v.y = acc[nt][3];
            *(float2*)(out + (size_t)(row0 + r0 + 8) * 256 + col) = v;
        }
    }
}

// ---------------- agg epilogue helper ----------------
__device__ __forceinline__ void warp_epilogue(
    const float acc[8][4], const float* __restrict__ bias,
    float* __restrict__ dst, int dstride, int rt, int nt_base, int gid, int tid4)
{
    const int row0 = rt * 16 + gid;
    #pragma unroll
    for (int nt = 0; nt < 8; nt++) {
        const int col = (nt_base + nt) * 8 + 2 * tid4;
        const float b0 = bias[col], b1 = bias[col + 1];
        float2 v0, v1;
        v0.x = fmaxf(acc[nt][0] + b0, 0.f);
        v0.y = fmaxf(acc[nt][1] + b1, 0.f);
        v1.x = fmaxf(acc[nt][2] + b0, 0.f);
        v1.y = fmaxf(acc[nt][3] + b1, 0.f);
        *(float2*)(dst + row0 * dstride + col) = v0;
        *(float2*)(dst + (row0 + 8) * dstride + col) = v1;
    }
}

// ---------------- Fused kernel: one CTA = one node (64 paths) ----------------
__global__ __launch_bounds__(256, 2) void agg_mma_kernel(
    const int* __restrict__ prel, const int* __restrict__ pnbr,
    const int* __restrict__ attrs,
    const float* __restrict__ b1, const float* __restrict__ b2,
    const float* __restrict__ ab2, const float* __restrict__ A3,
    const float* __restrict__ ab3, float* __restrict__ out)
{
    extern __shared__ float sm[];
    const int n = blockIdx.x;
    const int t = threadIdx.x;
    const int w = t >> 5, lane = t & 31;
    const int gid = lane >> 2, tid4 = lane & 3;
    const int rt = w & 3;
    const int ch = w >> 2;
    const int nt_base = ch * 8;

    int* s_rel = (int*)(sm + OFF_REL);
    int* s_nbr = (int*)(sm + OFF_NBR);
    int* s_att = (int*)(sm + OFF_ATT);

    sm[OFF_B1 + t] = b1[t];
    if (t < 128) {
        sm[OFF_B2 + t] = b2[t];
        sm[OFF_SE + t] = g_se[n * 128 + t];
        sm[OFF_AB2 + t] = ab2[t];
        sm[OFF_A3 + t] = A3[t];
        s_rel[t] = prel[n * 128 + t];
    }
    if (t < 64) s_nbr[t] = pnbr[n * 64 + t];
    for (int i = t; i < 512; i += 256) s_att[i] = attrs[n * 512 + i];
    __syncthreads();

    // ---- gather: h1[k][0:256] = relu(b1 + Tr1 + Tr2 + Tu + sum_a Ta) ----
    {
        float* s_h1 = sm + OFF_H1;
        const int ks = t >> 6;
        const int jj = t & 63;
        for (int kb = 0; kb < 16; kb++) {
            const int k = kb * 4 + ks;
            const int r0 = s_rel[2 * k], r1 = s_rel[2 * k + 1], nb = s_nbr[k];
            float4 acc = *(const float4*)(sm + OFF_B1 + jj * 4);
            float4 v;
            v = ((const float4*)(g_Tr1 + r0 * 256))[jj];
            acc.x += v.x; acc.y += v.y; acc.z += v.z; acc.w += v.w;
            v = ((const float4*)(g_Tr2 + r1 * 256))[jj];
            acc.x += v.x; acc.y += v.y; acc.z += v.z; acc.w += v.w;
            v = ((const float4*)(g_Tu + (size_t)nb * 256))[jj];
            acc.x += v.x; acc.y += v.y; acc.z += v.z; acc.w += v.w;
            #pragma unroll
            for (int a = 0; a < 8; a++) {
                v = ((const float4*)(g_Ta + (size_t)s_att[k * 8 + a] * 256))[jj];
                acc.x += v.x; acc.y += v.y; acc.z += v.z; acc.w += v.w;
            }
            acc.x = fmaxf(acc.x, 0.f); acc.y = fmaxf(acc.y, 0.f);
            acc.z = fmaxf(acc.z, 0.f); acc.w = fmaxf(acc.w, 0.f);
            ((float4*)(s_h1 + k * H1S))[jj] = acc;
        }
    }
    __syncthreads();

    float acc[8][4];

    // ---- GEMM1: h = relu(h1 @ W2 + b2) ----
    warp_gemm_g<8>(sm + OFF_H1 + rt * 16 * H1S, H1S, 32, g_W2f, 16, nt_base,
                   gid, tid4, lane, acc);
    warp_epilogue(acc, sm + OFF_B2, sm + OFF_H, HS, rt, nt_base, gid, tid4);
    __syncthreads();

    // ---- GEMM2: a1 = relu(h @ A1[0:128] + se) ----
    warp_gemm_g<8>(sm + OFF_H + rt * 16 * HS, HS, 16, g_A1f, 16, nt_base,
                   gid, tid4, lane, acc);
    warp_epilogue(acc, sm + OFF_SE, sm + OFF_H1, HS, rt, nt_base, gid, tid4);
    __syncthreads();

    // ---- GEMM3: a2 = relu(a1 @ A2 + ab2); logits fused ----
    warp_gemm_g<8>(sm + OFF_H1 + rt * 16 * HS, HS, 16, g_A2f, 16, nt_base,
                   gid, tid4, lane, acc);
    {
        float p0 = 0.f, p1 = 0.f;
        #pragma unroll
        for (int nt = 0; nt < 8; nt++) {
            const int col = (nt_base + nt) * 8 + 2 * tid4;
            const float b0 = sm[OFF_AB2 + col], b1v = sm[OFF_AB2 + col + 1];
            const float w0 = sm[OFF_A3 + col], w1 = sm[OFF_A3 + col + 1];
            p0 = fmaf(fmaxf(acc[nt][0] + b0, 0.f), w0, p0);
            p0 = fmaf(fmaxf(acc[nt][1] + b1v, 0.f), w1, p0);
            p1 = fmaf(fmaxf(acc[nt][2] + b0, 0.f), w0, p1);
            p1 = fmaf(fmaxf(acc[nt][3] + b1v, 0.f), w1, p1);
        }
        p0 += __shfl_xor_sync(0xffffffffu, p0, 1);
        p0 += __shfl_xor_sync(0xffffffffu, p0, 2);
        p1 += __shfl_xor_sync(0xffffffffu, p1, 1);
        p1 += __shfl_xor_sync(0xffffffffu, p1, 2);
        if (tid4 == 0) {
            sm[OFF_LGP + ch * 64 + rt * 16 + gid] = p0;
            sm[OFF_LGP + ch * 64 + rt * 16 + gid + 8] = p1;
        }
    }
    __syncthreads();

    // ---- softmax over 64 logits (warp 0) ----
    if (t < 32) {
        const float a3b = ab3[0];
        float l0 = a3b + sm[OFF_LGP + t] + sm[OFF_LGP + 64 + t];
        float l1 = a3b + sm[OFF_LGP + t + 32] + sm[OFF_LGP + 96 + t];
        float m = fmaxf(l0, l1);
        #pragma unroll
        for (int off = 16; off; off >>= 1)
            m = fmaxf(m, __shfl_xor_sync(0xffffffffu, m, off));
        float e0 = expf(l0 - m), e1 = expf(l1 - m);
        float s = e0 + e1;
        #pragma unroll
        for (int off = 16; off; off >>= 1)
            s += __shfl_xor_sync(0xffffffffu, s, off);
        const float inv = 1.f / s;
        sm[OFF_LG + t] = e0 * inv;
        sm[OFF_LG + t + 32] = e1 * inv;
    }
    __syncthreads();

    // ---- out[n][d] = sum_k w[k] * h[k][d] ----
    if (t < 128) {
        const float* hb = sm + OFF_H;
        float acc2 = 0.f;
        #pragma unroll 4
        for (int k = 0; k < 64; k++)
            acc2 = fmaf(sm[OFF_LG + k], hb[k * HS + t], acc2);
        out[(size_t)n * 128 + t] = acc2;
    }
}

// -------------------------------------------------------------------------
extern "C" void kernel_launch(void* const* d_in, const int* in_sizes, int n_in,
                              void* d_out, int out_size)
{
    const int*   nodes = (const int*)d_in[0];
    const int*   prel  = (const int*)d_in[1];
    const int*   pnbr  = (const int*)d_in[2];
    const int*   attrs = (const int*)d_in[3];
    const float* u2e   = (const float*)d_in[4];
    const float* r2e   = (const float*)d_in[5];
    const float* ua2e  = (const float*)d_in[6];
    const float* W1    = (const float*)d_in[7];
    const float* b1    = (const float*)d_in[8];
    const float* W2    = (const float*)d_in[9];
    const float* b2    = (const float*)d_in[10];
    const float* A1    = (const float*)d_in[11];
    const float* ab1   = (const float*)d_in[12];
    const float* A2    = (const float*)d_in[13];
    const float* ab2   = (const float*)d_in[14];
    const float* A3    = (const float*)d_in[15];
    const float* ab3   = (const float*)d_in[16];
    float* out = (float*)d_out;

    // Fragment builders (tiny)
    frag_kernel<<<128, 256>>>(W2, A1, A2);
    frag_w1_kernel<<<256, 256>>>(W1);
    se_kernel<<<NN, 128>>>(nodes, u2e, A1, ab1);

    // All four folded tables in one tensor-core launch
    mma_table_kernel<<<TU_CTAS + TA_CTAS + 2, 256>>>(u2e, ua2e, r2e);

    cudaFuncSetAttribute(agg_mma_kernel,
                         cudaFuncAttributeMaxDynamicSharedMemorySize, SMEM_BYTES);
    agg_mma_kernel<<<NN, 256, SMEM_BYTES>>>(prel, pnbr, attrs,
                                            b1, b2, ab2, A3, ab3, out);
}